// round 1
// baseline (speedup 1.0000x reference)
#include <cuda_runtime.h>

// LSTM_51204600103202: B=65536, T=7, H=128, input dim 1.
// gates = x_t*W_ih + h @ W_hh^T + (b_ih+b_hh); i,f,g,o PyTorch order.
// c' = sig(f)*c + sig(i)*tanh(g); h' = sig(o)*tanh(c'); pred = h'@W_out^T + b_out.
// Step s consumes x0 (s==0) else x[:, s-1]. Output pred per step -> [B,7,1].

#define H 128
#define T 7
#define M 32         // batch rows per CTA
#define KC 32        // K-chunk staged per iteration
#define NTHREADS 256
#define WT_STRIDE 516  // 512 + 4 pad (floats), keeps float4 alignment

__device__ __forceinline__ float tanh_fast(float v) {
    float y;
    asm("tanh.approx.f32 %0, %1;" : "=f"(y) : "f"(v));
    return y;
}
__device__ __forceinline__ float sigmoid_fast(float v) {
    return 0.5f * tanh_fast(0.5f * v) + 0.5f;
}

// Swizzled offset into transposed W tile: element (k within chunk, g row of W_hh).
// XOR of bits [2:4] of g by (k>>3) spreads the 8 same-g writers across banks;
// the +4 row pad spreads k. Reads stay float4-aligned (xor only touches bits>=2).
__device__ __forceinline__ int wofs(int k, int g) {
    return k * WT_STRIDE + (g ^ (((k >> 3) & 7) << 2));
}

__global__ __launch_bounds__(NTHREADS, 2)
void lstm_kernel(const float* __restrict__ x,
                 const float* __restrict__ x0,
                 const float* __restrict__ W_ih,
                 const float* __restrict__ W_hh,
                 const float* __restrict__ b_ih,
                 const float* __restrict__ b_hh,
                 const float* __restrict__ W_out,
                 const float* __restrict__ b_out,
                 float* __restrict__ out)
{
    extern __shared__ float smem[];
    float* Wt    = smem;                 // KC * WT_STRIDE = 16512 floats
    float* hs    = Wt + KC * WT_STRIDE;  // M * H = 4096 floats, [row][unit]
    float* sbias = hs + M * H;           // 512
    float* swih  = sbias + 512;          // 512
    float* swout = swih + 512;           // 128

    const int tid = threadIdx.x;
    const int tx = tid & 31;    // unit group: units u0..u0+3
    const int ty = tid >> 5;    // row group: rows r0..r0+3 (warp == row group)
    const int u0 = tx * 4;
    const int r0 = ty * 4;
    const int rowBase = blockIdx.x * M;

    // One-time SMEM init: combined bias, W_ih, W_out; zero h.
    for (int i = tid; i < 512; i += NTHREADS) {
        sbias[i] = b_ih[i] + b_hh[i];
        swih[i]  = W_ih[i];
    }
    if (tid < H) swout[tid] = W_out[tid];
    for (int i = tid; i < M * H; i += NTHREADS) hs[i] = 0.0f;
    __syncthreads();

    float wout[4];
#pragma unroll
    for (int j = 0; j < 4; j++) wout[j] = swout[u0 + j];
    const float bout = b_out[0];

    float c[4][4];  // [row i][unit j] cell state, thread-private
#pragma unroll
    for (int i = 0; i < 4; i++)
#pragma unroll
        for (int j = 0; j < 4; j++) c[i][j] = 0.0f;

    for (int s = 0; s < T; s++) {
        // ---- init accumulators: bias + x_t * W_ih ----
        float xv[4];
#pragma unroll
        for (int i = 0; i < 4; i++) {
            int row = rowBase + r0 + i;
            xv[i] = (s == 0) ? x0[row] : x[row * T + (s - 1)];
        }
        float acc[4][4][4];  // [gate g][row i][unit j]
#pragma unroll
        for (int g = 0; g < 4; g++) {
#pragma unroll
            for (int j = 0; j < 4; j++) {
                float b  = sbias[g * H + u0 + j];
                float wi = swih[g * H + u0 + j];
#pragma unroll
                for (int i = 0; i < 4; i++)
                    acc[g][i][j] = b + xv[i] * wi;
            }
        }

        // ---- gates += h @ W_hh^T, K staged in chunks of KC ----
        for (int kc = 0; kc < H; kc += KC) {
            __syncthreads();  // prior chunk's Wt reads / prior step's hs writes done
            // Stage W_hh[:, kc:kc+KC] transposed+swizzled into Wt.
            // idx -> (g = idx>>3, kk = (idx&7)*4): coalesced float4 global reads.
#pragma unroll
            for (int it = 0; it < 16; it++) {
                int idx = tid + it * NTHREADS;      // 0..4095
                int g  = idx >> 3;                  // W_hh row 0..511
                int kk = (idx & 7) * 4;             // k within chunk
                float4 w4 = *reinterpret_cast<const float4*>(&W_hh[g * H + kc + kk]);
                Wt[wofs(kk + 0, g)] = w4.x;
                Wt[wofs(kk + 1, g)] = w4.y;
                Wt[wofs(kk + 2, g)] = w4.z;
                Wt[wofs(kk + 3, g)] = w4.w;
            }
            __syncthreads();

#pragma unroll 4
            for (int k = 0; k < KC; k++) {
                float hv[4];
#pragma unroll
                for (int i = 0; i < 4; i++)
                    hv[i] = hs[(r0 + i) * H + kc + k];  // broadcast within warp
#pragma unroll
                for (int g = 0; g < 4; g++) {
                    const float4 w = *reinterpret_cast<const float4*>(
                        &Wt[wofs(k, g * H + u0)]);
#pragma unroll
                    for (int i = 0; i < 4; i++) {
                        acc[g][i][0] += hv[i] * w.x;
                        acc[g][i][1] += hv[i] * w.y;
                        acc[g][i][2] += hv[i] * w.z;
                        acc[g][i][3] += hv[i] * w.w;
                    }
                }
            }
        }

        __syncthreads();  // all hs reads of this step done before overwrite

        // ---- nonlinearity, state update, prediction ----
#pragma unroll
        for (int i = 0; i < 4; i++) {
            float hn[4];
            float p = 0.0f;
#pragma unroll
            for (int j = 0; j < 4; j++) {
                float ig = sigmoid_fast(acc[0][i][j]);
                float fg = sigmoid_fast(acc[1][i][j]);
                float gg = tanh_fast(acc[2][i][j]);
                float og = sigmoid_fast(acc[3][i][j]);
                float cn = fg * c[i][j] + ig * gg;
                c[i][j] = cn;
                hn[j] = og * tanh_fast(cn);
                p += hn[j] * wout[j];
            }
            *reinterpret_cast<float4*>(&hs[(r0 + i) * H + u0]) =
                make_float4(hn[0], hn[1], hn[2], hn[3]);
            // warp (== row group) holds all 128 units: full reduction over tx
#pragma unroll
            for (int off = 16; off > 0; off >>= 1)
                p += __shfl_xor_sync(0xffffffffu, p, off);
            if (tx == 0)
                out[(rowBase + r0 + i) * T + s] = p + bout;
        }
    }
}

extern "C" void kernel_launch(void* const* d_in, const int* in_sizes, int n_in,
                              void* d_out, int out_size)
{
    const float* x     = (const float*)d_in[0];
    const float* x0    = (const float*)d_in[1];
    const float* W_ih  = (const float*)d_in[2];
    const float* W_hh  = (const float*)d_in[3];
    const float* b_ih  = (const float*)d_in[4];
    const float* b_hh  = (const float*)d_in[5];
    const float* W_out = (const float*)d_in[6];
    const float* b_out = (const float*)d_in[7];
    float* out = (float*)d_out;

    const int B = in_sizes[1];  // x0 has B elements
    const int smem_bytes = (KC * WT_STRIDE + M * H + 512 + 512 + 128) * (int)sizeof(float);

    cudaFuncSetAttribute(lstm_kernel,
                         cudaFuncAttributeMaxDynamicSharedMemorySize, smem_bytes);

    lstm_kernel<<<B / M, NTHREADS, smem_bytes>>>(
        x, x0, W_ih, W_hh, b_ih, b_hh, W_out, b_out, out);
}

// round 3
// speedup vs baseline: 6.2497x; 6.2497x over previous
#include <cuda_runtime.h>
#include <cuda_bf16.h>
#include <cstdint>

// LSTM B=65536, T=7, H=128, fused recurrence via warp-level mma.sync (bf16->f32).
// PTX target is plain compute_103 (no 'a' features): tcgen05 unavailable; mma.sync
// (sm_80+) is the tensor path. Per CTA: 64 batch rows. Per step:
//   gates[64,512] = h[64,128] @ W'^T   (W' = W_hh rows permuted to j = unit*4+gate)
// computed as 8 warps x (64x64 slice), K=128, accum fp32 in registers.
// Epilogue: shfl-regroup gates, add bias + x*W_ih, fp32 nonlinearities,
// c in registers, h -> bf16 SMEM (double-buffered), pred via warp+SMEM reduce.

#define T 7
#define MTILE 64
#define NTH 256
#define WSTR 136   // bf16 elems per W' row (odd multiple of 8 -> 16B granule pitch 17)
#define HSTR 136

#define W_OFF   0u
#define H0_OFF  139264u               // 512*136*2
#define H1_OFF  156672u               // +64*136*2
#define F32_OFF 174080u               // +64*136*2
#define F_BIAS 0
#define F_WIH  512
#define F_WOUT 1024
#define F_XS   1152                   // 64 rows x 8 slots
#define F_PRED 1664                   // 2 x (64 rows x 8 warps)
#define F_COUNT 2688
#define SMEM_TOTAL (174080 + F_COUNT * 4)

static __device__ __forceinline__ uint32_t smem_u32(const void* p) {
    uint32_t a;
    asm("{ .reg .u64 t; cvta.to.shared.u64 t, %1; cvt.u32.u64 %0, t; }"
        : "=r"(a) : "l"(p));
    return a;
}
static __device__ __forceinline__ float tanh_fast(float v) {
    float y; asm("tanh.approx.f32 %0, %1;" : "=f"(y) : "f"(v)); return y;
}
static __device__ __forceinline__ float sigmoid_fast(float v) {
    return 0.5f * tanh_fast(0.5f * v) + 0.5f;
}
static __device__ __forceinline__ uint32_t pack_bf16x2(float lo, float hi) {
    uint32_t r;
    asm("cvt.rn.bf16x2.f32 %0, %1, %2;" : "=r"(r) : "f"(hi), "f"(lo));
    return r;
}

#define LDSM_X4(r0, r1, r2, r3, addr) \
    asm volatile("ldmatrix.sync.aligned.m8n8.x4.shared.b16 {%0,%1,%2,%3}, [%4];" \
        : "=r"(r0), "=r"(r1), "=r"(r2), "=r"(r3) : "r"(addr))

#define MMA16816(D, A, B0, B1) \
    asm volatile("mma.sync.aligned.m16n8k16.row.col.f32.bf16.bf16.f32 " \
        "{%0,%1,%2,%3}, {%4,%5,%6,%7}, {%8,%9}, {%0,%1,%2,%3};" \
        : "+f"((D)[0]), "+f"((D)[1]), "+f"((D)[2]), "+f"((D)[3]) \
        : "r"((A)[0]), "r"((A)[1]), "r"((A)[2]), "r"((A)[3]), "r"(B0), "r"(B1))

__global__ __launch_bounds__(NTH, 1)
void lstm_mma_kernel(const float* __restrict__ x,
                     const float* __restrict__ x0,
                     const float* __restrict__ W_ih,
                     const float* __restrict__ W_hh,
                     const float* __restrict__ b_ih,
                     const float* __restrict__ b_hh,
                     const float* __restrict__ W_out,
                     const float* __restrict__ b_out,
                     float* __restrict__ out)
{
    extern __shared__ char smem[];
    const uint32_t sb = smem_u32(smem);
    float* f32s = (float*)(smem + F32_OFF);

    const int tid  = threadIdx.x;
    const int wid  = tid >> 5;
    const int lane = tid & 31;
    const int q    = lane & 3;
    const int par  = q & 1;       // 0: handles row r, 1: row r+8 (after gate swap)
    const int hu   = q >> 1;      // unit-within-pair select
    const int rowBase = blockIdx.x * MTILE;

    // ---- one-time staging ----
    // W' rows j = u*4+g  <- W_hh row g*128+u, bf16, pitch WSTR
#pragma unroll
    for (int it = 0; it < 64; it++) {
        int idx = tid + it * NTH;            // 0..16383
        int j   = idx >> 5;                  // 0..511
        int kq  = (idx & 31) * 4;            // 0..124
        int src = (j & 3) * 128 + (j >> 2);
        float4 w4 = *(const float4*)(W_hh + src * 128 + kq);
        uint32_t o = (uint32_t)(j * WSTR + kq) * 2;
        *(uint32_t*)(smem + o)     = pack_bf16x2(w4.x, w4.y);
        *(uint32_t*)(smem + o + 4) = pack_bf16x2(w4.z, w4.w);
    }
    for (int i = tid; i < (int)(64 * HSTR * 2 / 4); i += NTH)   // zero h0 buffer
        *(uint32_t*)(smem + H0_OFF + i * 4) = 0u;
    for (int j = tid; j < 512; j += NTH) {                      // permuted bias/W_ih
        int u = j >> 2, g = j & 3, src = g * 128 + u;
        f32s[F_BIAS + j] = b_ih[src] + b_hh[src];
        f32s[F_WIH + j]  = W_ih[src];
    }
    if (tid < 128) f32s[F_WOUT + tid] = W_out[tid];
    for (int i = tid; i < MTILE * 8; i += NTH) {
        int row = i >> 3, s = i & 7;
        f32s[F_XS + i] = (s == 0) ? x0[rowBase + row]
                                  : x[(rowBase + row) * T + (s > 6 ? 6 : s - 1)];
    }
    __syncthreads();

    const float bout = b_out[0];

    float cst[4][8];
#pragma unroll
    for (int mi = 0; mi < 4; mi++)
#pragma unroll
        for (int ni = 0; ni < 8; ni++) cst[mi][ni] = 0.0f;

    // per-thread ldmatrix byte offsets
    const uint32_t aOff = (uint32_t)(((lane & 15) * HSTR + ((lane >> 4) & 1) * 8) * 2);
    const uint32_t bOff = (uint32_t)(((wid * 64 + ((lane >> 4) & 1) * 8 + (lane & 7)) * WSTR
                                      + ((lane >> 3) & 1) * 8) * 2);

    for (int s = 0; s < T; s++) {
        const uint32_t hcur = (s & 1) ? H1_OFF : H0_OFF;
        const uint32_t hnxt = (s & 1) ? H0_OFF : H1_OFF;

        float acc[4][8][4];
#pragma unroll
        for (int mi = 0; mi < 4; mi++)
#pragma unroll
            for (int ni = 0; ni < 8; ni++)
#pragma unroll
                for (int e = 0; e < 4; e++) acc[mi][ni][e] = 0.0f;

        // ---- MMA phase: K = 8 chunks of 16 ----
#pragma unroll
        for (int kc = 0; kc < 8; kc++) {
            uint32_t a[4][4];
#pragma unroll
            for (int mi = 0; mi < 4; mi++)
                LDSM_X4(a[mi][0], a[mi][1], a[mi][2], a[mi][3],
                        sb + hcur + aOff + (uint32_t)((mi * 16 * HSTR + kc * 16) * 2));
#pragma unroll
            for (int np = 0; np < 4; np++) {
                uint32_t b0, b1, b2, b3;
                LDSM_X4(b0, b1, b2, b3,
                        sb + W_OFF + bOff + (uint32_t)((np * 16 * WSTR + kc * 16) * 2));
#pragma unroll
                for (int mi = 0; mi < 4; mi++) {
                    MMA16816(acc[mi][np * 2],     a[mi], b0, b1);
                    MMA16816(acc[mi][np * 2 + 1], a[mi], b2, b3);
                }
            }
        }

        // ---- epilogue ----
        const int pb = F_PRED + (s & 1) * 512;
#pragma unroll
        for (int mi = 0; mi < 4; mi++) {
            const int row_eff = mi * 16 + (lane >> 2) + par * 8;
            const float xv = f32s[F_XS + row_eff * 8 + s];
            float pred = 0.0f;
#pragma unroll
            for (int ni = 0; ni < 8; ni++) {
                // gate swap within lane pair (q even holds i,f; q odd holds g,o)
                float s0 = par ? acc[mi][ni][0] : acc[mi][ni][2];
                float s1 = par ? acc[mi][ni][1] : acc[mi][ni][3];
                float r0 = __shfl_xor_sync(0xffffffffu, s0, 1);
                float r1 = __shfl_xor_sync(0xffffffffu, s1, 1);
                float gi = par ? r0 : acc[mi][ni][0];
                float gf = par ? r1 : acc[mi][ni][1];
                float gg = par ? acc[mi][ni][2] : r0;
                float go = par ? acc[mi][ni][3] : r1;

                const int u = wid * 16 + ni * 2 + hu;        // global unit 0..127
                const float4 b4 = *(const float4*)&f32s[F_BIAS + u * 4];
                const float4 w4 = *(const float4*)&f32s[F_WIH + u * 4];
                gi += b4.x + xv * w4.x;
                gf += b4.y + xv * w4.y;
                gg += b4.z + xv * w4.z;
                go += b4.w + xv * w4.w;

                float ig = sigmoid_fast(gi);
                float fg = sigmoid_fast(gf);
                float g_ = tanh_fast(gg);
                float og = sigmoid_fast(go);
                float cn = fg * cst[mi][ni] + ig * g_;
                cst[mi][ni] = cn;
                float hn = og * tanh_fast(cn);
                pred += hn * f32s[F_WOUT + u];

                *(__nv_bfloat16*)(smem + hnxt + (uint32_t)((row_eff * HSTR + u) * 2)) =
                    __float2bfloat16(hn);
            }
            pred += __shfl_xor_sync(0xffffffffu, pred, 2);   // combine unit halves
            if (q < 2) f32s[pb + row_eff * 8 + wid] = pred;
        }

        __syncthreads();   // h(next) + pred partials visible; hcur reads done

        if (tid < MTILE) {
            float p = bout;
#pragma unroll
            for (int w = 0; w < 8; w++) p += f32s[pb + tid * 8 + w];
            out[(rowBase + tid) * T + s] = p;
        }
    }
}

extern "C" void kernel_launch(void* const* d_in, const int* in_sizes, int n_in,
                              void* d_out, int out_size)
{
    const float* x     = (const float*)d_in[0];
    const float* x0    = (const float*)d_in[1];
    const float* W_ih  = (const float*)d_in[2];
    const float* W_hh  = (const float*)d_in[3];
    const float* b_ih  = (const float*)d_in[4];
    const float* b_hh  = (const float*)d_in[5];
    const float* W_out = (const float*)d_in[6];
    const float* b_out = (const float*)d_in[7];
    float* out = (float*)d_out;

    const int B = in_sizes[1];   // x0 element count

    cudaFuncSetAttribute(lstm_mma_kernel,
                         cudaFuncAttributeMaxDynamicSharedMemorySize, SMEM_TOTAL);

    lstm_mma_kernel<<<B / MTILE, NTH, SMEM_TOTAL>>>(
        x, x0, W_ih, W_hh, b_ih, b_hh, W_out, b_out, out);
}

// round 4
// speedup vs baseline: 7.2331x; 1.1574x over previous
#include <cuda_runtime.h>
#include <cuda_bf16.h>
#include <cstdint>

// LSTM B=65536, T=7, H=128, fused recurrence via warp-level mma.sync (bf16->f32).
// Per CTA: 64 batch rows, 512 threads / 16 warps. Per step:
//   gates[64,512] = h[64,128] @ W'^T   (W' = W_hh rows permuted to j = unit*4+gate)
// warp w owns a 64x32 N-slice (units w*8..w*8+7), K=128, fp32 accum in regs.
// Epilogue: shfl-regroup gates, bias + x*W_ih, fp32 nonlinearities, c in regs,
// h -> bf16 SMEM (double-buffered), pred via shfl + 16-warp SMEM reduce.

#define T 7
#define MTILE 64
#define NTH 512
#define WSTR 136   // bf16 elems per W' row (17x16B pitch -> ldmatrix conflict-free)
#define HSTR 136

#define W_OFF   0u
#define H0_OFF  139264u               // 512*136*2
#define H1_OFF  156672u               // +64*136*2
#define F32_OFF 174080u               // +64*136*2
#define F_BIAS 0
#define F_WIH  512
#define F_WOUT 1024
#define F_XS   1152                   // 64 rows x 8 slots
#define F_PRED 1664                   // 2 x (64 rows x 16 warps)
#define F_COUNT 3712
#define SMEM_TOTAL (174080 + F_COUNT * 4)   // 188928

static __device__ __forceinline__ uint32_t smem_u32(const void* p) {
    uint32_t a;
    asm("{ .reg .u64 t; cvta.to.shared.u64 t, %1; cvt.u32.u64 %0, t; }"
        : "=r"(a) : "l"(p));
    return a;
}
static __device__ __forceinline__ float tanh_fast(float v) {
    float y; asm("tanh.approx.f32 %0, %1;" : "=f"(y) : "f"(v)); return y;
}
static __device__ __forceinline__ float sigmoid_fast(float v) {
    return 0.5f * tanh_fast(0.5f * v) + 0.5f;
}
static __device__ __forceinline__ uint32_t pack_bf16x2(float lo, float hi) {
    uint32_t r;
    asm("cvt.rn.bf16x2.f32 %0, %1, %2;" : "=r"(r) : "f"(hi), "f"(lo));
    return r;
}

#define LDSM_X4(r0, r1, r2, r3, addr) \
    asm volatile("ldmatrix.sync.aligned.m8n8.x4.shared.b16 {%0,%1,%2,%3}, [%4];" \
        : "=r"(r0), "=r"(r1), "=r"(r2), "=r"(r3) : "r"(addr))

#define MMA16816(D, A, B0, B1) \
    asm volatile("mma.sync.aligned.m16n8k16.row.col.f32.bf16.bf16.f32 " \
        "{%0,%1,%2,%3}, {%4,%5,%6,%7}, {%8,%9}, {%0,%1,%2,%3};" \
        : "+f"((D)[0]), "+f"((D)[1]), "+f"((D)[2]), "+f"((D)[3]) \
        : "r"((A)[0]), "r"((A)[1]), "r"((A)[2]), "r"((A)[3]), "r"(B0), "r"(B1))

__global__ __launch_bounds__(NTH, 1)
void lstm_mma_kernel(const float* __restrict__ x,
                     const float* __restrict__ x0,
                     const float* __restrict__ W_ih,
                     const float* __restrict__ W_hh,
                     const float* __restrict__ b_ih,
                     const float* __restrict__ b_hh,
                     const float* __restrict__ W_out,
                     const float* __restrict__ b_out,
                     float* __restrict__ out)
{
    extern __shared__ char smem[];
    const uint32_t sb = smem_u32(smem);
    float* f32s = (float*)(smem + F32_OFF);

    const int tid  = threadIdx.x;
    const int wid  = tid >> 5;        // 0..15
    const int lane = tid & 31;
    const int q    = lane & 3;
    const int par  = q & 1;           // gate-pair parity (row +0 / +8 after swap)
    const int hu   = q >> 1;          // unit-within-pair select
    const int rowBase = blockIdx.x * MTILE;

    // ---- one-time staging ----
    // W' rows j = u*4+g  <- W_hh row g*128+u, bf16, pitch WSTR
#pragma unroll
    for (int it = 0; it < 32; it++) {
        int idx = tid + it * NTH;            // 0..16383
        int j   = idx >> 5;                  // 0..511
        int kq  = (idx & 31) * 4;            // 0..124
        int src = (j & 3) * 128 + (j >> 2);
        float4 w4 = *(const float4*)(W_hh + src * 128 + kq);
        uint32_t o = (uint32_t)(j * WSTR + kq) * 2;
        *(uint32_t*)(smem + o)     = pack_bf16x2(w4.x, w4.y);
        *(uint32_t*)(smem + o + 4) = pack_bf16x2(w4.z, w4.w);
    }
    for (int i = tid; i < (int)(64 * HSTR * 2 / 4); i += NTH)   // zero h0 buffer
        *(uint32_t*)(smem + H0_OFF + i * 4) = 0u;
    for (int j = tid; j < 512; j += NTH) {                      // permuted bias/W_ih
        int u = j >> 2, g = j & 3, src = g * 128 + u;
        f32s[F_BIAS + j] = b_ih[src] + b_hh[src];
        f32s[F_WIH + j]  = W_ih[src];
    }
    if (tid < 128) f32s[F_WOUT + tid] = W_out[tid];
    if (tid < MTILE * 8) {
        int row = tid >> 3, s = tid & 7;
        f32s[F_XS + tid] = (s == 0) ? x0[rowBase + row]
                                    : x[(rowBase + row) * T + (s > 6 ? 6 : s - 1)];
    }
    __syncthreads();

    const float bout = b_out[0];

    float cst[4][4];
#pragma unroll
    for (int mi = 0; mi < 4; mi++)
#pragma unroll
        for (int ni = 0; ni < 4; ni++) cst[mi][ni] = 0.0f;

    // per-thread ldmatrix byte offsets
    const uint32_t aOff = (uint32_t)(((lane & 15) * HSTR + ((lane >> 4) & 1) * 8) * 2);
    const uint32_t bOff = (uint32_t)(((wid * 32 + ((lane >> 4) & 1) * 8 + (lane & 7)) * WSTR
                                      + ((lane >> 3) & 1) * 8) * 2);

    for (int s = 0; s < T; s++) {
        const uint32_t hcur = (s & 1) ? H1_OFF : H0_OFF;
        const uint32_t hnxt = (s & 1) ? H0_OFF : H1_OFF;

        float acc[4][4][4];
#pragma unroll
        for (int mi = 0; mi < 4; mi++)
#pragma unroll
            for (int ni = 0; ni < 4; ni++)
#pragma unroll
                for (int e = 0; e < 4; e++) acc[mi][ni][e] = 0.0f;

        // ---- MMA phase: K = 8 chunks of 16 ----
#pragma unroll
        for (int kc = 0; kc < 8; kc++) {
            uint32_t a[4][4];
#pragma unroll
            for (int mi = 0; mi < 4; mi++)
                LDSM_X4(a[mi][0], a[mi][1], a[mi][2], a[mi][3],
                        sb + hcur + aOff + (uint32_t)((mi * 16 * HSTR + kc * 16) * 2));
#pragma unroll
            for (int np = 0; np < 2; np++) {
                uint32_t b0, b1, b2, b3;
                LDSM_X4(b0, b1, b2, b3,
                        sb + W_OFF + bOff + (uint32_t)((np * 16 * WSTR + kc * 16) * 2));
#pragma unroll
                for (int mi = 0; mi < 4; mi++) {
                    MMA16816(acc[mi][np * 2],     a[mi], b0, b1);
                    MMA16816(acc[mi][np * 2 + 1], a[mi], b2, b3);
                }
            }
        }

        // ---- epilogue ----
        const int pb = F_PRED + (s & 1) * 1024;
#pragma unroll
        for (int mi = 0; mi < 4; mi++) {
            const int row_eff = mi * 16 + (lane >> 2) + par * 8;
            const float xv = f32s[F_XS + row_eff * 8 + s];
            float pred = 0.0f;
#pragma unroll
            for (int ni = 0; ni < 4; ni++) {
                // gate swap within lane pair (q even holds i,f; q odd holds g,o)
                float s0 = par ? acc[mi][ni][0] : acc[mi][ni][2];
                float s1 = par ? acc[mi][ni][1] : acc[mi][ni][3];
                float r0 = __shfl_xor_sync(0xffffffffu, s0, 1);
                float r1 = __shfl_xor_sync(0xffffffffu, s1, 1);
                float gi = par ? r0 : acc[mi][ni][0];
                float gf = par ? r1 : acc[mi][ni][1];
                float gg = par ? acc[mi][ni][2] : r0;
                float go = par ? acc[mi][ni][3] : r1;

                const int u = wid * 8 + ni * 2 + hu;         // global unit 0..127
                const float4 b4 = *(const float4*)&f32s[F_BIAS + u * 4];
                const float4 w4 = *(const float4*)&f32s[F_WIH + u * 4];
                gi += b4.x + xv * w4.x;
                gf += b4.y + xv * w4.y;
                gg += b4.z + xv * w4.z;
                go += b4.w + xv * w4.w;

                float ig = sigmoid_fast(gi);
                float fg = sigmoid_fast(gf);
                float g_ = tanh_fast(gg);
                float og = sigmoid_fast(go);
                float cn = fg * cst[mi][ni] + ig * g_;
                cst[mi][ni] = cn;
                float hn = og * tanh_fast(cn);
                pred += hn * f32s[F_WOUT + u];

                *(__nv_bfloat16*)(smem + hnxt + (uint32_t)((row_eff * HSTR + u) * 2)) =
                    __float2bfloat16(hn);
            }
            pred += __shfl_xor_sync(0xffffffffu, pred, 2);   // combine unit halves
            if (q < 2) f32s[pb + row_eff * 16 + wid] = pred;
        }

        __syncthreads();   // h(next) + pred partials visible; hcur reads done

        if (tid < MTILE) {
            float p = bout;
#pragma unroll
            for (int w = 0; w < 16; w++) p += f32s[pb + tid * 16 + w];
            out[(rowBase + tid) * T + s] = p;
        }
    }
}

extern "C" void kernel_launch(void* const* d_in, const int* in_sizes, int n_in,
                              void* d_out, int out_size)
{
    const float* x     = (const float*)d_in[0];
    const float* x0    = (const float*)d_in[1];
    const float* W_ih  = (const float*)d_in[2];
    const float* W_hh  = (const float*)d_in[3];
    const float* b_ih  = (const float*)d_in[4];
    const float* b_hh  = (const float*)d_in[5];
    const float* W_out = (const float*)d_in[6];
    const float* b_out = (const float*)d_in[7];
    float* out = (float*)d_out;

    const int B = in_sizes[1];   // x0 element count

    cudaFuncSetAttribute(lstm_mma_kernel,
                         cudaFuncAttributeMaxDynamicSharedMemorySize, SMEM_TOTAL);

    lstm_mma_kernel<<<B / MTILE, NTH, SMEM_TOTAL>>>(
        x, x0, W_ih, W_hh, b_ih, b_hh, W_out, b_out, out);
}